// round 1
// baseline (speedup 1.0000x reference)
#include <cuda_runtime.h>
#include <math.h>

#define BATCH  4
#define NHEADS 16
#define HEAD   64
#define SEQ    2048
#define EMBED  1024   // NHEADS*HEAD

// ---------------- scratch (device globals: allocation-free) ----------------
__device__ float g_q[BATCH * NHEADS * SEQ * HEAD];     // [B,H,S,D]
__device__ float g_k[BATCH * NHEADS * SEQ * HEAD];
__device__ float g_v[BATCH * NHEADS * SEQ * HEAD];
__device__ float g_attn[BATCH * SEQ * EMBED];          // [B,S,H*D] concat order

// ============================================================================
// Kernel 1: fused QKV projection.
// For each (b,h): X[S,E] @ W{q,k,v}[E,D] -> Q/K/V [S,D].
// One 64x32 X tile is loaded once and reused for all three weight matrices.
// Block: 256 threads (16x16), each thread computes a 4x4 micro-tile per matrix.
// ============================================================================
__global__ __launch_bounds__(256) void qkv_kernel(
    const float* __restrict__ x,
    const float* __restrict__ Wq,
    const float* __restrict__ Wk,
    const float* __restrict__ Wv)
{
    __shared__ float xs[64][33];
    __shared__ float wqs[32][65];
    __shared__ float wks[32][65];
    __shared__ float wvs[32][65];

    const int bh = blockIdx.y;
    const int b  = bh / NHEADS;
    const int h  = bh % NHEADS;
    const int s0 = blockIdx.x * 64;

    const int tid = threadIdx.x;
    const int tx  = tid & 15;
    const int ty  = tid >> 4;

    const float* xb  = x  + ((size_t)b * SEQ + s0) * EMBED;
    const float* wqb = Wq + (size_t)h * EMBED * HEAD;
    const float* wkb = Wk + (size_t)h * EMBED * HEAD;
    const float* wvb = Wv + (size_t)h * EMBED * HEAD;

    float aq[4][4] = {};
    float ak[4][4] = {};
    float av[4][4] = {};

    for (int kc = 0; kc < EMBED; kc += 32) {
        // X tile 64x32 (rows of 32 floats -> 128B coalesced)
        #pragma unroll
        for (int i = tid; i < 64 * 32; i += 256) {
            int r = i >> 5, c = i & 31;
            xs[r][c] = xb[(size_t)r * EMBED + kc + c];
        }
        // W tiles 32x64 (rows of 64 floats contiguous)
        #pragma unroll
        for (int i = tid; i < 32 * 64; i += 256) {
            int e = i >> 6, d = i & 63;
            wqs[e][d] = wqb[(size_t)(kc + e) * HEAD + d];
            wks[e][d] = wkb[(size_t)(kc + e) * HEAD + d];
            wvs[e][d] = wvb[(size_t)(kc + e) * HEAD + d];
        }
        __syncthreads();

        #pragma unroll 8
        for (int e = 0; e < 32; e++) {
            float xr[4];
            #pragma unroll
            for (int i = 0; i < 4; i++) xr[i] = xs[ty * 4 + i][e];
            float wq4[4], wk4[4], wv4[4];
            #pragma unroll
            for (int j = 0; j < 4; j++) {
                wq4[j] = wqs[e][tx * 4 + j];
                wk4[j] = wks[e][tx * 4 + j];
                wv4[j] = wvs[e][tx * 4 + j];
            }
            #pragma unroll
            for (int i = 0; i < 4; i++)
                #pragma unroll
                for (int j = 0; j < 4; j++) {
                    aq[i][j] += xr[i] * wq4[j];
                    ak[i][j] += xr[i] * wk4[j];
                    av[i][j] += xr[i] * wv4[j];
                }
        }
        __syncthreads();
    }

    // store to [B,H,S,D]
    #pragma unroll
    for (int i = 0; i < 4; i++) {
        size_t row = (size_t)bh * SEQ + s0 + ty * 4 + i;
        #pragma unroll
        for (int j = 0; j < 4; j++) {
            size_t idx = row * HEAD + tx * 4 + j;
            g_q[idx] = aq[i][j];
            g_k[idx] = ak[i][j];
            g_v[idx] = av[i][j];
        }
    }
}

// ============================================================================
// Kernel 2: causal flash attention per (b,h).
// BM=64 queries per block, BN=32 keys per inner tile, online softmax.
// Output written in [B,S,H,D] concat layout for the projection GEMM.
// ============================================================================
__global__ __launch_bounds__(256) void attn_kernel()
{
    __shared__ float qs[64][65];
    __shared__ float ks[32][65];
    __shared__ float vs[32][65];
    __shared__ float ps[64][33];

    const int bh = blockIdx.y;
    const int b  = bh / NHEADS;
    const int h  = bh % NHEADS;
    const int qt = blockIdx.x;
    const int q0 = qt * 64;

    const int tid = threadIdx.x;
    const int tx  = tid & 15;
    const int ty  = tid >> 4;

    const float* qp = g_q + ((size_t)bh * SEQ + q0) * HEAD;
    const float* kp = g_k + (size_t)bh * SEQ * HEAD;
    const float* vp = g_v + (size_t)bh * SEQ * HEAD;

    // load + pre-scale Q tile
    #pragma unroll
    for (int i = tid; i < 64 * 64; i += 256) {
        int r = i >> 6, d = i & 63;
        qs[r][d] = qp[(size_t)r * HEAD + d] * 0.125f;  // 1/sqrt(64)
    }

    float acc[4][4] = {};
    float m[4], l[4];
    #pragma unroll
    for (int i = 0; i < 4; i++) { m[i] = -1e30f; l[i] = 0.0f; }

    const int nkt = 2 * qt + 2;  // 32-key tiles covering keys [0, q0+64)

    for (int kt = 0; kt < nkt; kt++) {
        const int k0 = kt * 32;
        __syncthreads();  // prior PV done before overwriting ks/vs
        #pragma unroll
        for (int i = tid; i < 32 * 64; i += 256) {
            int r = i >> 6, d = i & 63;
            ks[r][d] = kp[(size_t)(k0 + r) * HEAD + d];
            vs[r][d] = vp[(size_t)(k0 + r) * HEAD + d];
        }
        __syncthreads();

        // S = Q K^T  (each thread: 4 rows x 2 key-cols)
        float s[4][2] = {};
        #pragma unroll 8
        for (int d = 0; d < 64; d++) {
            float qr[4];
            #pragma unroll
            for (int i = 0; i < 4; i++) qr[i] = qs[ty * 4 + i][d];
            float kr[2];
            #pragma unroll
            for (int j = 0; j < 2; j++) kr[j] = ks[tx * 2 + j][d];
            #pragma unroll
            for (int i = 0; i < 4; i++)
                #pragma unroll
                for (int j = 0; j < 2; j++)
                    s[i][j] += qr[i] * kr[j];
        }

        // causal mask
        #pragma unroll
        for (int i = 0; i < 4; i++) {
            int qi = q0 + ty * 4 + i;
            #pragma unroll
            for (int j = 0; j < 2; j++)
                if (k0 + tx * 2 + j > qi) s[i][j] = -1e30f;
        }

        // row max across the 16 tx lanes
        float mt[4], nm[4], sc[4], sum[4];
        #pragma unroll
        for (int i = 0; i < 4; i++) {
            mt[i] = fmaxf(s[i][0], s[i][1]);
            #pragma unroll
            for (int o = 1; o < 16; o <<= 1)
                mt[i] = fmaxf(mt[i], __shfl_xor_sync(0xffffffffu, mt[i], o));
            nm[i] = fmaxf(m[i], mt[i]);
            sc[i] = __expf(m[i] - nm[i]);
        }

        // p = exp(s - nm), row sum
        #pragma unroll
        for (int i = 0; i < 4; i++) {
            float p0 = __expf(s[i][0] - nm[i]);
            float p1 = __expf(s[i][1] - nm[i]);
            ps[ty * 4 + i][tx * 2 + 0] = p0;
            ps[ty * 4 + i][tx * 2 + 1] = p1;
            sum[i] = p0 + p1;
            #pragma unroll
            for (int o = 1; o < 16; o <<= 1)
                sum[i] += __shfl_xor_sync(0xffffffffu, sum[i], o);
            l[i] = l[i] * sc[i] + sum[i];
            m[i] = nm[i];
            #pragma unroll
            for (int c = 0; c < 4; c++) acc[i][c] *= sc[i];
        }
        __syncthreads();

        // O += P V   (each thread: 4 rows x 4 d-cols)
        #pragma unroll 8
        for (int j = 0; j < 32; j++) {
            float vr[4];
            #pragma unroll
            for (int c = 0; c < 4; c++) vr[c] = vs[j][tx * 4 + c];
            #pragma unroll
            for (int i = 0; i < 4; i++) {
                float p = ps[ty * 4 + i][j];
                #pragma unroll
                for (int c = 0; c < 4; c++)
                    acc[i][c] += p * vr[c];
            }
        }
    }

    // epilogue: normalize, write to [B,S,H,D]
    #pragma unroll
    for (int i = 0; i < 4; i++) {
        float inv = 1.0f / l[i];
        size_t row = ((size_t)b * SEQ + q0 + ty * 4 + i) * NHEADS + h;
        #pragma unroll
        for (int c = 0; c < 4; c++)
            g_attn[row * HEAD + tx * 4 + c] = acc[i][c] * inv;
    }
}

// ============================================================================
// Kernel 3: output projection. out[n,e] = sum_f attn[n,f] * Wo[e,f] + bo[e]
// N = B*S = 8192, E = 1024.
// ============================================================================
__global__ __launch_bounds__(256) void proj_kernel(
    const float* __restrict__ Wo,
    const float* __restrict__ bo,
    float* __restrict__ out)
{
    __shared__ float as[64][33];
    __shared__ float ws[64][33];   // ws[e][f]

    const int e0 = blockIdx.x * 64;
    const int n0 = blockIdx.y * 64;
    const int tid = threadIdx.x;
    const int tx  = tid & 15;
    const int ty  = tid >> 4;

    float acc[4][4] = {};

    for (int f0 = 0; f0 < EMBED; f0 += 32) {
        #pragma unroll
        for (int i = tid; i < 64 * 32; i += 256) {
            int r = i >> 5, c = i & 31;
            as[r][c] = g_attn[(size_t)(n0 + r) * EMBED + f0 + c];
            ws[r][c] = Wo[(size_t)(e0 + r) * EMBED + f0 + c];
        }
        __syncthreads();

        #pragma unroll 8
        for (int f = 0; f < 32; f++) {
            float ar[4];
            #pragma unroll
            for (int i = 0; i < 4; i++) ar[i] = as[ty * 4 + i][f];
            float wr[4];
            #pragma unroll
            for (int j = 0; j < 4; j++) wr[j] = ws[tx * 4 + j][f];
            #pragma unroll
            for (int i = 0; i < 4; i++)
                #pragma unroll
                for (int j = 0; j < 4; j++)
                    acc[i][j] += ar[i] * wr[j];
        }
        __syncthreads();
    }

    #pragma unroll
    for (int i = 0; i < 4; i++) {
        size_t row = (size_t)(n0 + ty * 4 + i) * EMBED;
        #pragma unroll
        for (int j = 0; j < 4; j++) {
            int e = e0 + tx * 4 + j;
            out[row + e] = acc[i][j] + bo[e];
        }
    }
}

// ============================================================================
extern "C" void kernel_launch(void* const* d_in, const int* in_sizes, int n_in,
                              void* d_out, int out_size)
{
    const float* x   = (const float*)d_in[0];   // [B,S,E]
    const float* Wq  = (const float*)d_in[1];   // [H,E,D]
    const float* Wk  = (const float*)d_in[2];
    const float* Wv  = (const float*)d_in[3];
    const float* Wo  = (const float*)d_in[4];   // [E,E]
    const float* bo  = (const float*)d_in[5];   // [E]
    float* out = (float*)d_out;                 // [B,S,E]

    (void)in_sizes; (void)n_in; (void)out_size;

    qkv_kernel<<<dim3(SEQ / 64, BATCH * NHEADS), 256>>>(x, Wq, Wk, Wv);
    attn_kernel<<<dim3(SEQ / 64, BATCH * NHEADS), 256>>>();
    proj_kernel<<<dim3(EMBED / 64, (BATCH * SEQ) / 64), 256>>>(Wo, bo, out);
}

// round 2
// speedup vs baseline: 1.3480x; 1.3480x over previous
#include <cuda_runtime.h>
#include <stdint.h>
#include <math.h>

#define BATCH  4
#define NHEADS 16
#define HEAD   64
#define SEQ    2048
#define EMBED  1024

// ---------------- scratch (device globals: allocation-free) ----------------
__device__ float g_q[BATCH * NHEADS * SEQ * HEAD];   // [B,H,S,D]
__device__ float g_k[BATCH * NHEADS * SEQ * HEAD];
__device__ float g_v[BATCH * NHEADS * SEQ * HEAD];
__device__ float g_attn[BATCH * SEQ * EMBED];        // [B,S,H*D]

// ---------------- tf32 mma helpers ----------------
__device__ __forceinline__ uint32_t f2tf32(float f) {
    uint32_t r;
    asm("cvt.rna.tf32.f32 %0, %1;" : "=r"(r) : "f"(f));
    return r;
}

// D = A(16x8,row) * B(8x8,col) + D, tf32 in, f32 out
__device__ __forceinline__ void mma8(float* c,
                                     uint32_t a0, uint32_t a1, uint32_t a2, uint32_t a3,
                                     uint32_t b0, uint32_t b1) {
    asm volatile(
        "mma.sync.aligned.m16n8k8.row.col.f32.tf32.tf32.f32 "
        "{%0,%1,%2,%3}, {%4,%5,%6,%7}, {%8,%9}, {%0,%1,%2,%3};"
        : "+f"(c[0]), "+f"(c[1]), "+f"(c[2]), "+f"(c[3])
        : "r"(a0), "r"(a1), "r"(a2), "r"(a3), "r"(b0), "r"(b1));
}

// ============================================================================
// Kernel 1: fused QKV projection, tensor cores.
// Per (b,h): X[S,E] @ [Wq|Wk|Wv][E,192].  Block tile 128(M) x 192(N), K-chunk 16.
// 8 warps as 4(M) x 2(N): warp tile 32 x 96.
// ============================================================================
__global__ __launch_bounds__(256, 1) void qkv_kernel(
    const float* __restrict__ x,
    const float* __restrict__ Wq,
    const float* __restrict__ Wk,
    const float* __restrict__ Wv)
{
    __shared__ uint32_t Xs[128][20];   // stride 20: frag reads conflict-free
    __shared__ uint32_t Ws[16][200];   // stride 200 (==8 mod 32): conflict-free

    const int bh = blockIdx.y;
    const int b  = bh / NHEADS;
    const int h  = bh % NHEADS;
    const int s0 = blockIdx.x * 128;

    const int tid  = threadIdx.x;
    const int lane = tid & 31;
    const int warp = tid >> 5;
    const int g    = lane >> 2;
    const int t4   = lane & 3;
    const int wm   = warp & 3;   // 0..3  (M)
    const int wn   = warp >> 2;  // 0..1  (N)

    const float* xb = x + ((size_t)b * SEQ + s0) * EMBED;
    const float* wbase[3] = { Wq + (size_t)h * EMBED * HEAD,
                              Wk + (size_t)h * EMBED * HEAD,
                              Wv + (size_t)h * EMBED * HEAD };

    float c[2][12][4];
    #pragma unroll
    for (int mi = 0; mi < 2; mi++)
        #pragma unroll
        for (int ni = 0; ni < 12; ni++)
            #pragma unroll
            for (int e = 0; e < 4; e++) c[mi][ni][e] = 0.0f;

    for (int kc = 0; kc < EMBED; kc += 16) {
        // X tile 128x16
        #pragma unroll
        for (int i = tid; i < 128 * 16; i += 256) {
            int r = i >> 4, cc = i & 15;
            Xs[r][cc] = f2tf32(xb[(size_t)r * EMBED + kc + cc]);
        }
        // W tile 16x192 (q|k|v)
        #pragma unroll
        for (int i = tid; i < 16 * 192; i += 256) {
            int k = i / 192, n = i % 192;
            const float* wp = wbase[n >> 6];
            Ws[k][n] = f2tf32(wp[(size_t)(kc + k) * HEAD + (n & 63)]);
        }
        __syncthreads();

        #pragma unroll
        for (int ks = 0; ks < 2; ks++) {
            const int kb = ks * 8;
            uint32_t a[2][4];
            #pragma unroll
            for (int mi = 0; mi < 2; mi++) {
                int r = wm * 32 + mi * 16;
                a[mi][0] = Xs[r + g    ][kb + t4];
                a[mi][1] = Xs[r + g + 8][kb + t4];
                a[mi][2] = Xs[r + g    ][kb + t4 + 4];
                a[mi][3] = Xs[r + g + 8][kb + t4 + 4];
            }
            #pragma unroll
            for (int ni = 0; ni < 12; ni++) {
                uint32_t b0 = Ws[kb + t4    ][wn * 96 + ni * 8 + g];
                uint32_t b1 = Ws[kb + t4 + 4][wn * 96 + ni * 8 + g];
                #pragma unroll
                for (int mi = 0; mi < 2; mi++)
                    mma8(c[mi][ni], a[mi][0], a[mi][1], a[mi][2], a[mi][3], b0, b1);
            }
        }
        __syncthreads();
    }

    // epilogue -> g_q/g_k/g_v [B,H,S,D]
    float* dst[3] = { g_q + (size_t)bh * SEQ * HEAD,
                      g_k + (size_t)bh * SEQ * HEAD,
                      g_v + (size_t)bh * SEQ * HEAD };
    #pragma unroll
    for (int mi = 0; mi < 2; mi++) {
        int r0 = s0 + wm * 32 + mi * 16 + g;
        #pragma unroll
        for (int ni = 0; ni < 12; ni++) {
            #pragma unroll
            for (int e = 0; e < 4; e++) {
                int n = wn * 96 + ni * 8 + t4 * 2 + (e & 1);
                int r = r0 + (e >= 2 ? 8 : 0);
                dst[n >> 6][(size_t)r * HEAD + (n & 63)] = c[mi][ni][e];
            }
        }
    }
}

// ============================================================================
// Kernel 2: causal flash attention, tensor cores.
// BM=128 queries/block (8 warps x 16 rows), BN=32 keys/tile, D=64.
// Q fragments resident in registers; P relayout via warp-private smem rows.
// ============================================================================
__global__ __launch_bounds__(256, 1) void attn_kernel()
{
    __shared__ uint32_t Ks[32][68];    // stride==4 mod 32: S-phase B reads conflict-free
    __shared__ uint32_t Vs[32][72];    // stride==8 mod 32: PV-phase B reads conflict-free
    __shared__ float    Ps[128][36];   // stride==4 mod 32: A-frag reads conflict-free

    const int bh = blockIdx.y;
    const int b  = bh / NHEADS;
    const int h  = bh % NHEADS;
    const int qt = blockIdx.x;
    const int q0 = qt * 128;

    const int tid  = threadIdx.x;
    const int lane = tid & 31;
    const int warp = tid >> 5;           // 0..7, owns rows q0 + warp*16 ..
    const int g    = lane >> 2;
    const int t4   = lane & 3;

    const float* qp = g_q + ((size_t)bh * SEQ + q0) * HEAD;
    const float* kp = g_k + (size_t)bh * SEQ * HEAD;
    const float* vp = g_v + (size_t)bh * SEQ * HEAD;

    // ---- stage Q through Ps (two 32-col rounds), build A-frags in regs ----
    uint32_t qa[8][4];
    #pragma unroll
    for (int round = 0; round < 2; round++) {
        const int c0 = round * 32;
        #pragma unroll
        for (int i = tid; i < 128 * 32; i += 256) {
            int r = i >> 5, cc = i & 31;
            Ps[r][cc] = qp[(size_t)r * HEAD + c0 + cc] * 0.125f;  // 1/sqrt(64)
        }
        __syncthreads();
        #pragma unroll
        for (int kf = 0; kf < 4; kf++) {
            int kfi = round * 4 + kf;
            int rr = warp * 16;
            qa[kfi][0] = f2tf32(Ps[rr + g    ][kf * 8 + t4]);
            qa[kfi][1] = f2tf32(Ps[rr + g + 8][kf * 8 + t4]);
            qa[kfi][2] = f2tf32(Ps[rr + g    ][kf * 8 + t4 + 4]);
            qa[kfi][3] = f2tf32(Ps[rr + g + 8][kf * 8 + t4 + 4]);
        }
        __syncthreads();
    }

    float o[8][4];
    #pragma unroll
    for (int dn = 0; dn < 8; dn++)
        #pragma unroll
        for (int e = 0; e < 4; e++) o[dn][e] = 0.0f;

    float m0 = -1e30f, m1 = -1e30f, l0 = 0.0f, l1 = 0.0f;

    const int nkt   = (qt + 1) * 4;                 // key tiles covering [0, q0+128)
    const int row0b = q0 + warp * 16;               // warp's first query row
    const int qmaxw = row0b + 15;                   // warp's last query row

    for (int kt = 0; kt < nkt; kt++) {
        const int k0 = kt * 32;
        __syncthreads();
        #pragma unroll
        for (int i = tid; i < 32 * 64; i += 256) {
            int r = i >> 6, d = i & 63;
            Ks[r][d] = f2tf32(kp[(size_t)(k0 + r) * HEAD + d]);
            Vs[r][d] = f2tf32(vp[(size_t)(k0 + r) * HEAD + d]);
        }
        __syncthreads();

        if (k0 > qmaxw) continue;   // tile fully masked for this warp

        // ---- S = Q K^T : 4 n-frags x 8 k-frags ----
        float s[4][4];
        #pragma unroll
        for (int nf = 0; nf < 4; nf++)
            #pragma unroll
            for (int e = 0; e < 4; e++) s[nf][e] = 0.0f;

        #pragma unroll
        for (int kf = 0; kf < 8; kf++) {
            #pragma unroll
            for (int nf = 0; nf < 4; nf++) {
                uint32_t b0 = Ks[nf * 8 + g][kf * 8 + t4];
                uint32_t b1 = Ks[nf * 8 + g][kf * 8 + t4 + 4];
                mma8(s[nf], qa[kf][0], qa[kf][1], qa[kf][2], qa[kf][3], b0, b1);
            }
        }

        // ---- causal mask ----
        const int r0 = row0b + g;
        const int r1 = r0 + 8;
        #pragma unroll
        for (int nf = 0; nf < 4; nf++) {
            int col0 = k0 + nf * 8 + t4 * 2;
            if (col0     > r0) s[nf][0] = -1e30f;
            if (col0 + 1 > r0) s[nf][1] = -1e30f;
            if (col0     > r1) s[nf][2] = -1e30f;
            if (col0 + 1 > r1) s[nf][3] = -1e30f;
        }

        // ---- online softmax ----
        float rm0 = -1e30f, rm1 = -1e30f;
        #pragma unroll
        for (int nf = 0; nf < 4; nf++) {
            rm0 = fmaxf(rm0, fmaxf(s[nf][0], s[nf][1]));
            rm1 = fmaxf(rm1, fmaxf(s[nf][2], s[nf][3]));
        }
        rm0 = fmaxf(rm0, __shfl_xor_sync(0xffffffffu, rm0, 1));
        rm0 = fmaxf(rm0, __shfl_xor_sync(0xffffffffu, rm0, 2));
        rm1 = fmaxf(rm1, __shfl_xor_sync(0xffffffffu, rm1, 1));
        rm1 = fmaxf(rm1, __shfl_xor_sync(0xffffffffu, rm1, 2));

        float nm0 = fmaxf(m0, rm0), nm1 = fmaxf(m1, rm1);
        float sc0 = __expf(m0 - nm0), sc1 = __expf(m1 - nm1);

        float sum0 = 0.0f, sum1 = 0.0f;
        const int rr = warp * 16;
        #pragma unroll
        for (int nf = 0; nf < 4; nf++) {
            float p0 = __expf(s[nf][0] - nm0);
            float p1 = __expf(s[nf][1] - nm0);
            float p2 = __expf(s[nf][2] - nm1);
            float p3 = __expf(s[nf][3] - nm1);
            Ps[rr + g    ][nf * 8 + t4 * 2    ] = p0;
            Ps[rr + g    ][nf * 8 + t4 * 2 + 1] = p1;
            Ps[rr + g + 8][nf * 8 + t4 * 2    ] = p2;
            Ps[rr + g + 8][nf * 8 + t4 * 2 + 1] = p3;
            sum0 += p0 + p1;
            sum1 += p2 + p3;
        }
        sum0 += __shfl_xor_sync(0xffffffffu, sum0, 1);
        sum0 += __shfl_xor_sync(0xffffffffu, sum0, 2);
        sum1 += __shfl_xor_sync(0xffffffffu, sum1, 1);
        sum1 += __shfl_xor_sync(0xffffffffu, sum1, 2);

        l0 = l0 * sc0 + sum0;  m0 = nm0;
        l1 = l1 * sc1 + sum1;  m1 = nm1;

        #pragma unroll
        for (int dn = 0; dn < 8; dn++) {
            o[dn][0] *= sc0; o[dn][1] *= sc0;
            o[dn][2] *= sc1; o[dn][3] *= sc1;
        }
        __syncwarp();

        // ---- O += P V : 4 k-frags (keys) x 8 n-frags (d) ----
        #pragma unroll
        for (int kf = 0; kf < 4; kf++) {
            uint32_t pa0 = f2tf32(Ps[rr + g    ][kf * 8 + t4]);
            uint32_t pa1 = f2tf32(Ps[rr + g + 8][kf * 8 + t4]);
            uint32_t pa2 = f2tf32(Ps[rr + g    ][kf * 8 + t4 + 4]);
            uint32_t pa3 = f2tf32(Ps[rr + g + 8][kf * 8 + t4 + 4]);
            #pragma unroll
            for (int dn = 0; dn < 8; dn++) {
                uint32_t b0 = Vs[kf * 8 + t4    ][dn * 8 + g];
                uint32_t b1 = Vs[kf * 8 + t4 + 4][dn * 8 + g];
                mma8(o[dn], pa0, pa1, pa2, pa3, b0, b1);
            }
        }
        __syncwarp();
    }

    // ---- epilogue: normalize, write [B,S,H,D] concat layout ----
    const float inv0 = 1.0f / l0;
    const float inv1 = 1.0f / l1;
    const int r0 = q0 + warp * 16 + g;
    float* ob = g_attn + (size_t)b * SEQ * EMBED + (size_t)h * HEAD;
    #pragma unroll
    for (int dn = 0; dn < 8; dn++) {
        int d = dn * 8 + t4 * 2;
        ob[(size_t)(r0    ) * EMBED + d    ] = o[dn][0] * inv0;
        ob[(size_t)(r0    ) * EMBED + d + 1] = o[dn][1] * inv0;
        ob[(size_t)(r0 + 8) * EMBED + d    ] = o[dn][2] * inv1;
        ob[(size_t)(r0 + 8) * EMBED + d + 1] = o[dn][3] * inv1;
    }
}

// ============================================================================
// Kernel 3: output projection, tensor cores.
// out[n,e] = sum_f attn[n,f] * Wo[e,f] + bo[e].  Block 128x128, warp 32x64.
// ============================================================================
__global__ __launch_bounds__(256) void proj_kernel(
    const float* __restrict__ Wo,
    const float* __restrict__ bo,
    float* __restrict__ out)
{
    __shared__ uint32_t As[128][20];
    __shared__ uint32_t Bs[16][136];   // stride==8 mod 32: frag reads conflict-free

    const int e0 = blockIdx.x * 128;
    const int n0 = blockIdx.y * 128;

    const int tid  = threadIdx.x;
    const int lane = tid & 31;
    const int warp = tid >> 5;
    const int g    = lane >> 2;
    const int t4   = lane & 3;
    const int wm   = warp & 3;   // 4 in M
    const int wn   = warp >> 2;  // 2 in N

    float c[2][8][4];
    #pragma unroll
    for (int mi = 0; mi < 2; mi++)
        #pragma unroll
        for (int ni = 0; ni < 8; ni++)
            #pragma unroll
            for (int e = 0; e < 4; e++) c[mi][ni][e] = 0.0f;

    for (int f0 = 0; f0 < EMBED; f0 += 16) {
        #pragma unroll
        for (int i = tid; i < 128 * 16; i += 256) {
            int r = i >> 4, cc = i & 15;
            As[r][cc] = f2tf32(g_attn[(size_t)(n0 + r) * EMBED + f0 + cc]);
        }
        #pragma unroll
        for (int i = tid; i < 16 * 128; i += 256) {
            int n = i >> 4, k = i & 15;
            Bs[k][n] = f2tf32(Wo[(size_t)(e0 + n) * EMBED + f0 + k]);
        }
        __syncthreads();

        #pragma unroll
        for (int ks = 0; ks < 2; ks++) {
            const int kb = ks * 8;
            uint32_t a[2][4];
            #pragma unroll
            for (int mi = 0; mi < 2; mi++) {
                int r = wm * 32 + mi * 16;
                a[mi][0] = As[r + g    ][kb + t4];
                a[mi][1] = As[r + g + 8][kb + t4];
                a[mi][2] = As[r + g    ][kb + t4 + 4];
                a[mi][3] = As[r + g + 8][kb + t4 + 4];
            }
            #pragma unroll
            for (int ni = 0; ni < 8; ni++) {
                uint32_t b0 = Bs[kb + t4    ][wn * 64 + ni * 8 + g];
                uint32_t b1 = Bs[kb + t4 + 4][wn * 64 + ni * 8 + g];
                #pragma unroll
                for (int mi = 0; mi < 2; mi++)
                    mma8(c[mi][ni], a[mi][0], a[mi][1], a[mi][2], a[mi][3], b0, b1);
            }
        }
        __syncthreads();
    }

    #pragma unroll
    for (int mi = 0; mi < 2; mi++) {
        int r0 = n0 + wm * 32 + mi * 16 + g;
        #pragma unroll
        for (int ni = 0; ni < 8; ni++) {
            int e = e0 + wn * 64 + ni * 8 + t4 * 2;
            out[(size_t)(r0    ) * EMBED + e    ] = c[mi][ni][0] + bo[e];
            out[(size_t)(r0    ) * EMBED + e + 1] = c[mi][ni][1] + bo[e + 1];
            out[(size_t)(r0 + 8) * EMBED + e    ] = c[mi][ni][2] + bo[e];
            out[(size_t)(r0 + 8) * EMBED + e + 1] = c[mi][ni][3] + bo[e + 1];
        }
    }
}

// ============================================================================
extern "C" void kernel_launch(void* const* d_in, const int* in_sizes, int n_in,
                              void* d_out, int out_size)
{
    const float* x  = (const float*)d_in[0];
    const float* Wq = (const float*)d_in[1];
    const float* Wk = (const float*)d_in[2];
    const float* Wv = (const float*)d_in[3];
    const float* Wo = (const float*)d_in[4];
    const float* bo = (const float*)d_in[5];
    float* out = (float*)d_out;

    (void)in_sizes; (void)n_in; (void)out_size;

    qkv_kernel<<<dim3(SEQ / 128, BATCH * NHEADS), 256>>>(x, Wq, Wk, Wv);
    attn_kernel<<<dim3(SEQ / 128, BATCH * NHEADS), 256>>>();
    proj_kernel<<<dim3(EMBED / 128, (BATCH * SEQ) / 128), 256>>>(Wo, bo, out);
}

// round 3
// speedup vs baseline: 3.8445x; 2.8521x over previous
#include <cuda_runtime.h>
#include <stdint.h>
#include <math.h>

#define BATCH  4
#define NHEADS 16
#define HEAD   64
#define SEQ    2048
#define EMBED  1024
#define QKVN   3072   // 3 * NHEADS * HEAD

// ---------------- scratch (device globals: allocation-free) ----------------
__device__ float g_q[BATCH * NHEADS * SEQ * HEAD];   // [B,H,S,D], pre-scaled by 1/8
__device__ float g_k[BATCH * NHEADS * SEQ * HEAD];
__device__ float g_v[BATCH * NHEADS * SEQ * HEAD];
__device__ float g_attn[BATCH * SEQ * EMBED];        // [B,S,H*D]

// ---------------- helpers ----------------
__device__ __forceinline__ uint32_t f2tf32(float f) {
    uint32_t r;
    asm("cvt.rna.tf32.f32 %0, %1;" : "=r"(r) : "f"(f));
    return r;
}

__device__ __forceinline__ void mma8(float* c,
                                     uint32_t a0, uint32_t a1, uint32_t a2, uint32_t a3,
                                     uint32_t b0, uint32_t b1) {
    asm volatile(
        "mma.sync.aligned.m16n8k8.row.col.f32.tf32.tf32.f32 "
        "{%0,%1,%2,%3}, {%4,%5,%6,%7}, {%8,%9}, {%0,%1,%2,%3};"
        : "+f"(c[0]), "+f"(c[1]), "+f"(c[2]), "+f"(c[3])
        : "r"(a0), "r"(a1), "r"(a2), "r"(a3), "r"(b0), "r"(b1));
}

__device__ __forceinline__ void cp16(void* smem, const void* gmem) {
    uint32_t sa = (uint32_t)__cvta_generic_to_shared(smem);
    asm volatile("cp.async.cg.shared.global [%0], [%1], 16;" :: "r"(sa), "l"(gmem));
}
#define CP_COMMIT() asm volatile("cp.async.commit_group;")
#define CP_WAIT0()  asm volatile("cp.async.wait_group 0;")

// ============================================================================
// Kernel 1: QKV as one GEMM.  X[8192,1024] @ Wall[1024,3072] -> scatter to
// g_q/g_k/g_v in [B,H,S,D].  Block 128x128, 2-stage cp.async pipeline.
// 8 warps = 4(M) x 2(N); warp tile 32x64.  Column n -> (mat, head, d).
// ============================================================================
__global__ __launch_bounds__(256) void qkv_kernel(
    const float* __restrict__ x,
    const float* __restrict__ Wq,
    const float* __restrict__ Wk,
    const float* __restrict__ Wv)
{
    __shared__ float As[2][128][20];   // [m][k], stride 20: frag reads conflict-free
    __shared__ float Bs[2][16][136];   // [k][n], stride 136 (==8 mod 32)

    const int n0 = blockIdx.x * 128;
    const int m0 = blockIdx.y * 128;

    const int tid  = threadIdx.x;
    const int lane = tid & 31;
    const int warp = tid >> 5;
    const int g    = lane >> 2;
    const int t4   = lane & 3;
    const int wm   = warp & 3;
    const int wn   = warp >> 1 >> 1;   // warp>>2

    const int mat = n0 >> 10;                    // 0=q 1=k 2=v (const per block)
    const float* wmat = (mat == 0) ? Wq : ((mat == 1) ? Wk : Wv);
    const int nn0 = n0 & 1023;                   // col base within matrix

    // --- per-thread staging descriptors (2 x 16B chunks each for A and B) ---
    // A: chunk -> r = chunk>>2, c4 = chunk&3
    int arA[2], acA[2];
    const float* agp[2];
    #pragma unroll
    for (int j = 0; j < 2; j++) {
        int chunk = tid + j * 256;
        arA[j] = chunk >> 2; acA[j] = (chunk & 3) * 4;
        agp[j] = x + (size_t)(m0 + arA[j]) * EMBED + acA[j];
    }
    // B: chunk -> k = chunk>>5, n4 = chunk&31; n = nn0 + n4*4 -> (h,d)
    int bkB[2], bcB[2];
    const float* bgp[2];
    #pragma unroll
    for (int j = 0; j < 2; j++) {
        int chunk = tid + j * 256;
        int k = chunk >> 5, n4 = chunk & 31;
        int n = nn0 + n4 * 4;
        int h = n >> 6, d = n & 63;
        bkB[j] = k; bcB[j] = n4 * 4;
        bgp[j] = wmat + ((size_t)h * EMBED + k) * HEAD + d;
    }

    float c[2][8][4];
    #pragma unroll
    for (int mi = 0; mi < 2; mi++)
        #pragma unroll
        for (int ni = 0; ni < 8; ni++)
            #pragma unroll
            for (int e = 0; e < 4; e++) c[mi][ni][e] = 0.0f;

    // --- prologue: stage 0 ---
    #pragma unroll
    for (int j = 0; j < 2; j++) {
        cp16(&As[0][arA[j]][acA[j]], agp[j]);
        cp16(&Bs[0][bkB[j]][bcB[j]], bgp[j]);
    }
    CP_COMMIT();
    CP_WAIT0();
    __syncthreads();

    const int NK = EMBED / 16;   // 64
    for (int it = 0; it < NK; it++) {
        const int buf = it & 1;
        if (it + 1 < NK) {
            const int kc = (it + 1) * 16;
            #pragma unroll
            for (int j = 0; j < 2; j++) {
                cp16(&As[buf ^ 1][arA[j]][acA[j]], agp[j] + kc);
                cp16(&Bs[buf ^ 1][bkB[j]][bcB[j]], bgp[j] + (size_t)kc * HEAD);
            }
            CP_COMMIT();
        }

        #pragma unroll
        for (int ks = 0; ks < 2; ks++) {
            const int kb = ks * 8;
            uint32_t a[2][4];
            #pragma unroll
            for (int mi = 0; mi < 2; mi++) {
                int r = wm * 32 + mi * 16;
                a[mi][0] = f2tf32(As[buf][r + g    ][kb + t4]);
                a[mi][1] = f2tf32(As[buf][r + g + 8][kb + t4]);
                a[mi][2] = f2tf32(As[buf][r + g    ][kb + t4 + 4]);
                a[mi][3] = f2tf32(As[buf][r + g + 8][kb + t4 + 4]);
            }
            #pragma unroll
            for (int ni = 0; ni < 8; ni++) {
                uint32_t b0 = f2tf32(Bs[buf][kb + t4    ][wn * 64 + ni * 8 + g]);
                uint32_t b1 = f2tf32(Bs[buf][kb + t4 + 4][wn * 64 + ni * 8 + g]);
                #pragma unroll
                for (int mi = 0; mi < 2; mi++)
                    mma8(c[mi][ni], a[mi][0], a[mi][1], a[mi][2], a[mi][3], b0, b1);
            }
        }

        CP_WAIT0();
        __syncthreads();
    }

    // --- epilogue: scatter to [B,H,S,D]; pre-scale Q by 1/8 ---
    const int b   = m0 >> 11;
    const int s0l = m0 & 2047;
    const int h   = (nn0 >> 6) + wn;             // this warp's head
    float* dstm = (mat == 0) ? g_q : ((mat == 1) ? g_k : g_v);
    float* dst  = dstm + ((size_t)(b * NHEADS + h) * SEQ) * HEAD;
    const float scale = (mat == 0) ? 0.125f : 1.0f;

    #pragma unroll
    for (int mi = 0; mi < 2; mi++) {
        int s0r = s0l + wm * 32 + mi * 16 + g;
        #pragma unroll
        for (int ni = 0; ni < 8; ni++) {
            int d = ni * 8 + t4 * 2;
            dst[(size_t)(s0r    ) * HEAD + d    ] = c[mi][ni][0] * scale;
            dst[(size_t)(s0r    ) * HEAD + d + 1] = c[mi][ni][1] * scale;
            dst[(size_t)(s0r + 8) * HEAD + d    ] = c[mi][ni][2] * scale;
            dst[(size_t)(s0r + 8) * HEAD + d + 1] = c[mi][ni][3] * scale;
        }
    }
}

// ============================================================================
// Kernel 2: causal flash attention, tensor cores + register-staged prefetch.
// BM=128 queries/block (8 warps x 16 rows), BN=32 keys/tile, D=64.
// ============================================================================
__global__ __launch_bounds__(256, 1) void attn_kernel()
{
    __shared__ uint32_t Ks[32][68];    // stride==4 mod 32
    __shared__ uint32_t Vs[32][72];    // stride==8 mod 32
    __shared__ float    Ps[128][36];   // stride==4 mod 32

    const int bh = blockIdx.y;
    const int b  = bh >> 4;
    const int h  = bh & 15;
    const int qt = blockIdx.x;
    const int q0 = qt * 128;

    const int tid  = threadIdx.x;
    const int lane = tid & 31;
    const int warp = tid >> 5;
    const int g    = lane >> 2;
    const int t4   = lane & 3;

    const float* qp = g_q + ((size_t)bh * SEQ + q0) * HEAD;
    const float* kp = g_k + (size_t)bh * SEQ * HEAD;
    const float* vp = g_v + (size_t)bh * SEQ * HEAD;

    // ---- stage Q (already pre-scaled) through Ps, build A-frags ----
    uint32_t qa[8][4];
    #pragma unroll
    for (int round = 0; round < 2; round++) {
        const int c0 = round * 32;
        #pragma unroll
        for (int i = tid; i < 128 * 32; i += 256) {
            int r = i >> 5, cc = i & 31;
            Ps[r][cc] = qp[(size_t)r * HEAD + c0 + cc];
        }
        __syncthreads();
        #pragma unroll
        for (int kf = 0; kf < 4; kf++) {
            int kfi = round * 4 + kf;
            int rr = warp * 16;
            qa[kfi][0] = f2tf32(Ps[rr + g    ][kf * 8 + t4]);
            qa[kfi][1] = f2tf32(Ps[rr + g + 8][kf * 8 + t4]);
            qa[kfi][2] = f2tf32(Ps[rr + g    ][kf * 8 + t4 + 4]);
            qa[kfi][3] = f2tf32(Ps[rr + g + 8][kf * 8 + t4 + 4]);
        }
        __syncthreads();
    }

    float o[8][4];
    #pragma unroll
    for (int dn = 0; dn < 8; dn++)
        #pragma unroll
        for (int e = 0; e < 4; e++) o[dn][e] = 0.0f;

    float m0 = -1e30f, m1 = -1e30f, l0 = 0.0f, l1 = 0.0f;

    const int nkt   = (qt + 1) * 4;
    const int row0b = q0 + warp * 16;
    const int qmaxw = row0b + 15;

    // per-thread element set for a 32x64 tile: 8 elements
    const int er = tid >> 3;            // wrong mapping? use i = tid + j*256
    (void)er;

    float rk[8], rv[8];
    // preload tile 0 into regs, then smem
    #pragma unroll
    for (int j = 0; j < 8; j++) {
        int i = tid + j * 256;
        int r = i >> 6, d = i & 63;
        rk[j] = kp[(size_t)r * HEAD + d];
        rv[j] = vp[(size_t)r * HEAD + d];
    }
    #pragma unroll
    for (int j = 0; j < 8; j++) {
        int i = tid + j * 256;
        int r = i >> 6, d = i & 63;
        Ks[r][d] = f2tf32(rk[j]);
        Vs[r][d] = f2tf32(rv[j]);
    }
    __syncthreads();

    for (int kt = 0; kt < nkt; kt++) {
        const int k0 = kt * 32;

        // prefetch next tile into registers (hidden under compute)
        if (kt + 1 < nkt) {
            const size_t nb = (size_t)(k0 + 32) * HEAD;
            #pragma unroll
            for (int j = 0; j < 8; j++) {
                int i = tid + j * 256;
                int r = i >> 6, d = i & 63;
                rk[j] = kp[nb + (size_t)r * HEAD + d];
                rv[j] = vp[nb + (size_t)r * HEAD + d];
            }
        }

        if (k0 <= qmaxw) {
            // ---- S = Q K^T ----
            float s[4][4];
            #pragma unroll
            for (int nf = 0; nf < 4; nf++)
                #pragma unroll
                for (int e = 0; e < 4; e++) s[nf][e] = 0.0f;

            #pragma unroll
            for (int kf = 0; kf < 8; kf++) {
                #pragma unroll
                for (int nf = 0; nf < 4; nf++) {
                    uint32_t b0 = Ks[nf * 8 + g][kf * 8 + t4];
                    uint32_t b1 = Ks[nf * 8 + g][kf * 8 + t4 + 4];
                    mma8(s[nf], qa[kf][0], qa[kf][1], qa[kf][2], qa[kf][3], b0, b1);
                }
            }

            // ---- causal mask ----
            const int r0 = row0b + g;
            const int r1 = r0 + 8;
            #pragma unroll
            for (int nf = 0; nf < 4; nf++) {
                int col0 = k0 + nf * 8 + t4 * 2;
                if (col0     > r0) s[nf][0] = -1e30f;
                if (col0 + 1 > r0) s[nf][1] = -1e30f;
                if (col0     > r1) s[nf][2] = -1e30f;
                if (col0 + 1 > r1) s[nf][3] = -1e30f;
            }

            // ---- online softmax ----
            float rm0 = -1e30f, rm1 = -1e30f;
            #pragma unroll
            for (int nf = 0; nf < 4; nf++) {
                rm0 = fmaxf(rm0, fmaxf(s[nf][0], s[nf][1]));
                rm1 = fmaxf(rm1, fmaxf(s[nf][2], s[nf][3]));
            }
            rm0 = fmaxf(rm0, __shfl_xor_sync(0xffffffffu, rm0, 1));
            rm0 = fmaxf(rm0, __shfl_xor_sync(0xffffffffu, rm0, 2));
            rm1 = fmaxf(rm1, __shfl_xor_sync(0xffffffffu, rm1, 1));
            rm1 = fmaxf(rm1, __shfl_xor_sync(0xffffffffu, rm1, 2));

            float nm0 = fmaxf(m0, rm0), nm1 = fmaxf(m1, rm1);
            float sc0 = __expf(m0 - nm0), sc1 = __expf(m1 - nm1);

            float sum0 = 0.0f, sum1 = 0.0f;
            const int rr = warp * 16;
            #pragma unroll
            for (int nf = 0; nf < 4; nf++) {
                float p0 = __expf(s[nf][0] - nm0);
                float p1 = __expf(s[nf][1] - nm0);
                float p2 = __expf(s[nf][2] - nm1);
                float p3 = __expf(s[nf][3] - nm1);
                Ps[rr + g    ][nf * 8 + t4 * 2    ] = p0;
                Ps[rr + g    ][nf * 8 + t4 * 2 + 1] = p1;
                Ps[rr + g + 8][nf * 8 + t4 * 2    ] = p2;
                Ps[rr + g + 8][nf * 8 + t4 * 2 + 1] = p3;
                sum0 += p0 + p1;
                sum1 += p2 + p3;
            }
            sum0 += __shfl_xor_sync(0xffffffffu, sum0, 1);
            sum0 += __shfl_xor_sync(0xffffffffu, sum0, 2);
            sum1 += __shfl_xor_sync(0xffffffffu, sum1, 1);
            sum1 += __shfl_xor_sync(0xffffffffu, sum1, 2);

            l0 = l0 * sc0 + sum0;  m0 = nm0;
            l1 = l1 * sc1 + sum1;  m1 = nm1;

            #pragma unroll
            for (int dn = 0; dn < 8; dn++) {
                o[dn][0] *= sc0; o[dn][1] *= sc0;
                o[dn][2] *= sc1; o[dn][3] *= sc1;
            }
            __syncwarp();

            // ---- O += P V ----
            #pragma unroll
            for (int kf = 0; kf < 4; kf++) {
                uint32_t pa0 = f2tf32(Ps[rr + g    ][kf * 8 + t4]);
                uint32_t pa1 = f2tf32(Ps[rr + g + 8][kf * 8 + t4]);
                uint32_t pa2 = f2tf32(Ps[rr + g    ][kf * 8 + t4 + 4]);
                uint32_t pa3 = f2tf32(Ps[rr + g + 8][kf * 8 + t4 + 4]);
                #pragma unroll
                for (int dn = 0; dn < 8; dn++) {
                    uint32_t b0 = Vs[kf * 8 + t4    ][dn * 8 + g];
                    uint32_t b1 = Vs[kf * 8 + t4 + 4][dn * 8 + g];
                    mma8(o[dn], pa0, pa1, pa2, pa3, b0, b1);
                }
            }
        }

        __syncthreads();
        if (kt + 1 < nkt) {
            #pragma unroll
            for (int j = 0; j < 8; j++) {
                int i = tid + j * 256;
                int r = i >> 6, d = i & 63;
                Ks[r][d] = f2tf32(rk[j]);
                Vs[r][d] = f2tf32(rv[j]);
            }
        }
        __syncthreads();
    }

    // ---- epilogue ----
    const float inv0 = 1.0f / l0;
    const float inv1 = 1.0f / l1;
    const int r0 = q0 + warp * 16 + g;
    float* ob = g_attn + (size_t)b * SEQ * EMBED + (size_t)h * HEAD;
    #pragma unroll
    for (int dn = 0; dn < 8; dn++) {
        int d = dn * 8 + t4 * 2;
        ob[(size_t)(r0    ) * EMBED + d    ] = o[dn][0] * inv0;
        ob[(size_t)(r0    ) * EMBED + d + 1] = o[dn][1] * inv0;
        ob[(size_t)(r0 + 8) * EMBED + d    ] = o[dn][2] * inv1;
        ob[(size_t)(r0 + 8) * EMBED + d + 1] = o[dn][3] * inv1;
    }
}

// ============================================================================
// Kernel 3: output projection GEMM with 2-stage cp.async.
// out[n,e] = sum_f attn[n,f] * Wo[e,f] + bo[e].  Block 128x128.
// B staged as [n][k] (Wo rows are contiguous in f == k).
// ============================================================================
__global__ __launch_bounds__(256) void proj_kernel(
    const float* __restrict__ Wo,
    const float* __restrict__ bo,
    float* __restrict__ out)
{
    __shared__ float As[2][128][20];   // [m][k]
    __shared__ float Bs[2][128][20];   // [n][k]

    const int e0 = blockIdx.x * 128;
    const int m0 = blockIdx.y * 128;

    const int tid  = threadIdx.x;
    const int lane = tid & 31;
    const int warp = tid >> 5;
    const int g    = lane >> 2;
    const int t4   = lane & 3;
    const int wm   = warp & 3;
    const int wn   = warp >> 2;

    int rr_[2], cc_[2];
    const float* agp[2];
    const float* bgp[2];
    #pragma unroll
    for (int j = 0; j < 2; j++) {
        int chunk = tid + j * 256;
        rr_[j] = chunk >> 2; cc_[j] = (chunk & 3) * 4;
        agp[j] = g_attn + (size_t)(m0 + rr_[j]) * EMBED + cc_[j];
        bgp[j] = Wo     + (size_t)(e0 + rr_[j]) * EMBED + cc_[j];
    }

    float c[2][8][4];
    #pragma unroll
    for (int mi = 0; mi < 2; mi++)
        #pragma unroll
        for (int ni = 0; ni < 8; ni++)
            #pragma unroll
            for (int e = 0; e < 4; e++) c[mi][ni][e] = 0.0f;

    #pragma unroll
    for (int j = 0; j < 2; j++) {
        cp16(&As[0][rr_[j]][cc_[j]], agp[j]);
        cp16(&Bs[0][rr_[j]][cc_[j]], bgp[j]);
    }
    CP_COMMIT();
    CP_WAIT0();
    __syncthreads();

    const int NK = EMBED / 16;
    for (int it = 0; it < NK; it++) {
        const int buf = it & 1;
        if (it + 1 < NK) {
            const int f = (it + 1) * 16;
            #pragma unroll
            for (int j = 0; j < 2; j++) {
                cp16(&As[buf ^ 1][rr_[j]][cc_[j]], agp[j] + f);
                cp16(&Bs[buf ^ 1][rr_[j]][cc_[j]], bgp[j] + f);
            }
            CP_COMMIT();
        }

        #pragma unroll
        for (int ks = 0; ks < 2; ks++) {
            const int kb = ks * 8;
            uint32_t a[2][4];
            #pragma unroll
            for (int mi = 0; mi < 2; mi++) {
                int r = wm * 32 + mi * 16;
                a[mi][0] = f2tf32(As[buf][r + g    ][kb + t4]);
                a[mi][1] = f2tf32(As[buf][r + g + 8][kb + t4]);
                a[mi][2] = f2tf32(As[buf][r + g    ][kb + t4 + 4]);
                a[mi][3] = f2tf32(As[buf][r + g + 8][kb + t4 + 4]);
            }
            #pragma unroll
            for (int ni = 0; ni < 8; ni++) {
                uint32_t b0 = f2tf32(Bs[buf][wn * 64 + ni * 8 + g][kb + t4]);
                uint32_t b1 = f2tf32(Bs[buf][wn * 64 + ni * 8 + g][kb + t4 + 4]);
                #pragma unroll
                for (int mi = 0; mi < 2; mi++)
                    mma8(c[mi][ni], a[mi][0], a[mi][1], a[mi][2], a[mi][3], b0, b1);
            }
        }

        CP_WAIT0();
        __syncthreads();
    }

    #pragma unroll
    for (int mi = 0; mi < 2; mi++) {
        int r0 = m0 + wm * 32 + mi * 16 + g;
        #pragma unroll
        for (int ni = 0; ni < 8; ni++) {
            int e = e0 + wn * 64 + ni * 8 + t4 * 2;
            out[(size_t)(r0    ) * EMBED + e    ] = c[mi][ni][0] + bo[e];
            out[(size_t)(r0    ) * EMBED + e + 1] = c[mi][ni][1] + bo[e + 1];
            out[(size_t)(r0 + 8) * EMBED + e    ] = c[mi][ni][2] + bo[e];
            out[(size_t)(r0 + 8) * EMBED + e + 1] = c[mi][ni][3] + bo[e + 1];
        }
    }
}

// ============================================================================
extern "C" void kernel_launch(void* const* d_in, const int* in_sizes, int n_in,
                              void* d_out, int out_size)
{
    const float* x  = (const float*)d_in[0];
    const float* Wq = (const float*)d_in[1];
    const float* Wk = (const float*)d_in[2];
    const float* Wv = (const float*)d_in[3];
    const float* Wo = (const float*)d_in[4];
    const float* bo = (const float*)d_in[5];
    float* out = (float*)d_out;

    (void)in_sizes; (void)n_in; (void)out_size;

    qkv_kernel<<<dim3(QKVN / 128, (BATCH * SEQ) / 128), 256>>>(x, Wq, Wk, Wv);
    attn_kernel<<<dim3(SEQ / 128, BATCH * NHEADS), 256>>>();
    proj_kernel<<<dim3(EMBED / 128, (BATCH * SEQ) / 128), 256>>>(Wo, bo, out);
}